// round 13
// baseline (speedup 1.0000x reference)
#include <cuda_runtime.h>
#include <mma.h>
#include <math.h>

using namespace nvcuda;

#define NA 8192
#define NV 4096
#define NN 12288      // NA + NV
#define FDIM 64
#define ADIM 128
#define QKVS 384
#define KAA 10
#define KVV 15
#define MAXDEG 30
#define LTOT 8
#define OUTD 128

// ---------------- device scratch (no allocations allowed) ----------------
__device__ float  g_h[NN * ADIM];
__device__ float  g_qkv[NN * QKVS];
__device__ float  g_wqkv[LTOT * ADIM * QKVS];
__device__ float4 g_apos4[NA];
__device__ float4 g_vpos4[NV];
__device__ int    g_aa[NA * KAA];
__device__ int    g_av[NV * KVV];
__device__ int    g_vv[NV * KVV];
__device__ int    g_Uidx[NN * MAXDEG];
__device__ float  g_Uew[NN * MAXDEG];
__device__ float  g_paas[NA * 8];
__device__ float  g_paad[NA * 8];
__device__ float  g_pavd[NV * 8];
__device__ float  g_pavs[NA * 8];
__device__ float  g_pvvs[NV * 8];
__device__ float  g_pvvd[NV * 8];
__device__ float  g_feat[NV * 640];
__device__ float  g_hidden[NV * ADIM];

// ---------------- double-buffered fp32 big-tile GEMM ----------------
// C[M,N] = A[M,K] @ B[K,N] (+bias)(+relu); grid=(M/128,N/128), 256 thr, 8x8/thr
__global__ __launch_bounds__(256, 2)
void gemm128(const float* __restrict__ A, const float* __restrict__ B,
             const float* __restrict__ bias, float* __restrict__ C,
             int K, int N, int doRelu, int ldc)
{
    __shared__ __align__(16) float As[2][8][128];
    __shared__ __align__(16) float Bs[2][8][128];
    int tid = threadIdx.x;
    int bm = blockIdx.x << 7, bn = blockIdx.y << 7;
    int arow = tid >> 1, acol = (tid & 1) << 2;
    int brow = tid >> 5, bcol = (tid & 31) << 2;
    int tx = tid & 15, ty = tid >> 4;

    const float* Ap = A + (size_t)(bm + arow) * K + acol;
    const float* Bp = B + (size_t)brow * N + bn + bcol;

    float acc[8][8];
#pragma unroll
    for (int i = 0; i < 8; ++i)
#pragma unroll
        for (int j = 0; j < 8; ++j) acc[i][j] = 0.f;

    {
        float4 av = *(const float4*)(Ap);
        float4 bv = *(const float4*)(Bp);
        As[0][acol + 0][arow] = av.x;
        As[0][acol + 1][arow] = av.y;
        As[0][acol + 2][arow] = av.z;
        As[0][acol + 3][arow] = av.w;
        *(float4*)&Bs[0][brow][bcol] = bv;
    }
    __syncthreads();

    int buf = 0;
    for (int k0 = 0; k0 < K; k0 += 8) {
        bool more = (k0 + 8) < K;
        float4 av2, bv2;
        if (more) {
            av2 = *(const float4*)(Ap + k0 + 8);
            bv2 = *(const float4*)(Bp + (size_t)(k0 + 8) * N);
        }
        float ar[8], br[8];
#pragma unroll
        for (int kk = 0; kk < 8; ++kk) {
            *(float4*)&ar[0] = *(const float4*)&As[buf][kk][ty << 3];
            *(float4*)&ar[4] = *(const float4*)&As[buf][kk][(ty << 3) + 4];
            *(float4*)&br[0] = *(const float4*)&Bs[buf][kk][tx << 3];
            *(float4*)&br[4] = *(const float4*)&Bs[buf][kk][(tx << 3) + 4];
#pragma unroll
            for (int i = 0; i < 8; ++i)
#pragma unroll
                for (int j = 0; j < 8; ++j)
                    acc[i][j] = fmaf(ar[i], br[j], acc[i][j]);
        }
        if (more) {
            As[buf ^ 1][acol + 0][arow] = av2.x;
            As[buf ^ 1][acol + 1][arow] = av2.y;
            As[buf ^ 1][acol + 2][arow] = av2.z;
            As[buf ^ 1][acol + 3][arow] = av2.w;
            *(float4*)&Bs[buf ^ 1][brow][bcol] = bv2;
            __syncthreads();
            buf ^= 1;
        }
    }

#pragma unroll
    for (int i = 0; i < 8; ++i) {
        int r = bm + (ty << 3) + i;
        float* Cr = C + (size_t)r * ldc + bn + (tx << 3);
#pragma unroll
        for (int j = 0; j < 8; ++j) {
            float vv = acc[i][j];
            if (bias) vv += bias[bn + (tx << 3) + j];
            if (doRelu) vv = fmaxf(vv, 0.f);
            Cr[j] = vv;
        }
    }
}

// ---------------- tf32 tensor-core GEMM (no bias / no relu) ----------------
// C[M,N] = A[M,K] @ B[K,N]; grid=(M/128,N/128), 256 thr = 8 warps (4m x 2n),
// each warp owns a 32x64 tile = 2x4 wmma m16n16k8 fragments. Same smem
// staging as gemm128: As[k][m] == col-major A, Bs[k][n] == row-major B.
__global__ __launch_bounds__(256, 2)
void gemm128_tf32(const float* __restrict__ A, const float* __restrict__ B,
                  float* __restrict__ C, int K, int N, int ldc)
{
    __shared__ __align__(16) float As[2][8][128];
    __shared__ __align__(16) float Bs[2][8][128];
    int tid = threadIdx.x;
    int warp = tid >> 5;
    int wm = warp >> 1;          // 0..3 -> m offset 32*wm
    int wn = warp & 1;           // 0..1 -> n offset 64*wn
    int bm = blockIdx.x << 7, bn = blockIdx.y << 7;
    int arow = tid >> 1, acol = (tid & 1) << 2;
    int brow = tid >> 5, bcol = (tid & 31) << 2;

    const float* Ap = A + (size_t)(bm + arow) * K + acol;
    const float* Bp = B + (size_t)brow * N + bn + bcol;

    wmma::fragment<wmma::accumulator, 16, 16, 8, float> cf[2][4];
#pragma unroll
    for (int i = 0; i < 2; ++i)
#pragma unroll
        for (int j = 0; j < 4; ++j) wmma::fill_fragment(cf[i][j], 0.f);

    {
        float4 av = *(const float4*)(Ap);
        float4 bv = *(const float4*)(Bp);
        As[0][acol + 0][arow] = av.x;
        As[0][acol + 1][arow] = av.y;
        As[0][acol + 2][arow] = av.z;
        As[0][acol + 3][arow] = av.w;
        *(float4*)&Bs[0][brow][bcol] = bv;
    }
    __syncthreads();

    int buf = 0;
    for (int k0 = 0; k0 < K; k0 += 8) {
        bool more = (k0 + 8) < K;
        float4 av2, bv2;
        if (more) {
            av2 = *(const float4*)(Ap + k0 + 8);
            bv2 = *(const float4*)(Bp + (size_t)(k0 + 8) * N);
        }

        wmma::fragment<wmma::matrix_a, 16, 16, 8, wmma::precision::tf32, wmma::col_major> af[2];
        wmma::fragment<wmma::matrix_b, 16, 16, 8, wmma::precision::tf32, wmma::row_major> bf[4];
#pragma unroll
        for (int i = 0; i < 2; ++i) {
            wmma::load_matrix_sync(af[i], &As[buf][0][wm * 32 + i * 16], 128);
#pragma unroll
            for (int e = 0; e < af[i].num_elements; ++e)
                af[i].x[e] = wmma::__float_to_tf32(af[i].x[e]);
        }
#pragma unroll
        for (int j = 0; j < 4; ++j) {
            wmma::load_matrix_sync(bf[j], &Bs[buf][0][wn * 64 + j * 16], 128);
#pragma unroll
            for (int e = 0; e < bf[j].num_elements; ++e)
                bf[j].x[e] = wmma::__float_to_tf32(bf[j].x[e]);
        }
#pragma unroll
        for (int i = 0; i < 2; ++i)
#pragma unroll
            for (int j = 0; j < 4; ++j)
                wmma::mma_sync(cf[i][j], af[i], bf[j], cf[i][j]);

        if (more) {
            As[buf ^ 1][acol + 0][arow] = av2.x;
            As[buf ^ 1][acol + 1][arow] = av2.y;
            As[buf ^ 1][acol + 2][arow] = av2.z;
            As[buf ^ 1][acol + 3][arow] = av2.w;
            *(float4*)&Bs[buf ^ 1][brow][bcol] = bv2;
            __syncthreads();
            buf ^= 1;
        }
    }

#pragma unroll
    for (int i = 0; i < 2; ++i)
#pragma unroll
        for (int j = 0; j < 4; ++j) {
            int r = bm + wm * 32 + i * 16;
            int c = bn + wn * 64 + j * 16;
            wmma::store_matrix_sync(C + (size_t)r * ldc + c, cf[i][j], ldc, wmma::mem_row_major);
        }
}

// ---------------- position packing: (x, y, z, |p|^2) ----------------
__global__ void pack_pos(const float* __restrict__ pos, float4* __restrict__ out, int n)
{
    int i = blockIdx.x * blockDim.x + threadIdx.x;
    if (i >= n) return;
    float x = pos[i * 3 + 0], y = pos[i * 3 + 1], z = pos[i * 3 + 2];
    out[i] = make_float4(x, y, z, x * x + y * y + z * z);
}

// ---------------- pack wq|wk|wv -> [L,128,384] ----------------
__global__ void pack_qkv(const float* __restrict__ wq, const float* __restrict__ wk,
                         const float* __restrict__ wv, float* __restrict__ out)
{
    int i = blockIdx.x * blockDim.x + threadIdx.x;
    if (i >= LTOT * ADIM * ADIM) return;
    int li = i / (ADIM * ADIM);
    int r = (i / ADIM) % ADIM;
    int c = i % ADIM;
    float* o = out + ((size_t)li * ADIM + r) * QKVS;
    o[c] = wq[i];
    o[ADIM + c] = wk[i];
    o[2 * ADIM + c] = wv[i];
}

// ---------------- strided copy of vox h0 into feat cols [0:128) ----------------
__global__ void copy_to_feat(const float* __restrict__ src, float* __restrict__ feat)
{
    int i = blockIdx.x * blockDim.x + threadIdx.x;
    if (i >= NV * ADIM) return;
    int r = i >> 7, c = i & 127;
    feat[(size_t)r * 640 + c] = src[i];
}

// ---------------- warp-cooperative brute-force KNN, 2 dst per warp ----------------
// Distributed sorted top-K across lanes per dst (lane j = j-th smallest (d2,idx),
// exact lexicographic == jax top_k stable tie-break). Fast path: single d2<=T
// trigger per dst; exact checks + whole-warp shuffle-up insert only in the rare
// slow path. d2 = |a|^2 + |b|^2 - 2 a.b exactly as reference.
template <int KK, bool EXCL>
__global__ __launch_bounds__(256)
void knn_warp2(const float4* __restrict__ dpos4, const float4* __restrict__ spos4,
               int Ns, int* __restrict__ outIdx)
{
    const int TS = 2048;
    const unsigned FULL = 0xffffffffu;
    __shared__ float4 s4[TS];
    int lane = threadIdx.x & 31;
    int warp = threadIdx.x >> 5;
    int d0 = blockIdx.x * 16 + warp * 2;
    int d1 = d0 + 1;

    float4 p0 = dpos4[d0];
    float4 p1 = dpos4[d1];

    const float INF = __int_as_float(0x7f800000);
    float ld0 = INF, ld1 = INF;
    int   li0 = 0x7fffffff, li1 = 0x7fffffff;
    float T0 = INF, T1 = INF;
    int   Ti0 = 0x7fffffff, Ti1 = 0x7fffffff;

    for (int t0 = 0; t0 < Ns; t0 += TS) {
        int tn = Ns - t0; if (tn > TS) tn = TS;
        __syncthreads();
        for (int i = threadIdx.x; i < tn; i += 256) s4[i] = spos4[t0 + i];
        __syncthreads();
        for (int j = lane; j < tn; j += 32) {
            int si = t0 + j;
            float4 qv = s4[j];
            float dot0 = fmaf(p0.z, qv.z, fmaf(p0.y, qv.y, p0.x * qv.x));
            float d20 = fmaf(-2.0f, dot0, p0.w + qv.w);
            float dot1 = fmaf(p1.z, qv.z, fmaf(p1.y, qv.y, p1.x * qv.x));
            float d21 = fmaf(-2.0f, dot1, p1.w + qv.w);
            bool trig0 = (d20 <= T0) && !(EXCL && si == d0);
            bool trig1 = (d21 <= T1) && !(EXCL && si == d1);
            if (__ballot_sync(FULL, trig0 || trig1)) {
                // --- dst0 slow path ---
                bool pass = trig0 && ((d20 < T0) || (d20 == T0 && si < Ti0));
                unsigned m = __ballot_sync(FULL, pass);
                while (m) {
                    int s = __ffs(m) - 1;
                    float cd = __shfl_sync(FULL, d20, s);
                    int   ci = __shfl_sync(FULL, si, s);
                    bool before = (cd < ld0) || (cd == ld0 && ci < li0);
                    unsigned bm = __ballot_sync(FULL, before);
                    float ud = __shfl_up_sync(FULL, ld0, 1);
                    int   ui = __shfl_up_sync(FULL, li0, 1);
                    int fb = __ffs(bm) - 1;
                    if (before) {
                        if (lane == fb) { ld0 = cd; li0 = ci; }
                        else            { ld0 = ud; li0 = ui; }
                    }
                    T0  = __shfl_sync(FULL, ld0, KK - 1);
                    Ti0 = __shfl_sync(FULL, li0, KK - 1);
                    pass = pass && (lane > s) && ((d20 < T0) || (d20 == T0 && si < Ti0));
                    m = __ballot_sync(FULL, pass);
                }
                // --- dst1 slow path ---
                pass = trig1 && ((d21 < T1) || (d21 == T1 && si < Ti1));
                m = __ballot_sync(FULL, pass);
                while (m) {
                    int s = __ffs(m) - 1;
                    float cd = __shfl_sync(FULL, d21, s);
                    int   ci = __shfl_sync(FULL, si, s);
                    bool before = (cd < ld1) || (cd == ld1 && ci < li1);
                    unsigned bm = __ballot_sync(FULL, before);
                    float ud = __shfl_up_sync(FULL, ld1, 1);
                    int   ui = __shfl_up_sync(FULL, li1, 1);
                    int fb = __ffs(bm) - 1;
                    if (before) {
                        if (lane == fb) { ld1 = cd; li1 = ci; }
                        else            { ld1 = ud; li1 = ui; }
                    }
                    T1  = __shfl_sync(FULL, ld1, KK - 1);
                    Ti1 = __shfl_sync(FULL, li1, KK - 1);
                    pass = pass && (lane > s) && ((d21 < T1) || (d21 == T1 && si < Ti1));
                    m = __ballot_sync(FULL, pass);
                }
            }
        }
    }
    if (lane < KK) {
        outIdx[d0 * KK + lane] = li0;
        outIdx[d1 * KK + lane] = li1;
    }
}

// ---------------- per-row 128->8 projection (edge MLP first layer halves)
__global__ void proj8_kernel(const float* __restrict__ H, int Nrows,
                             const float* __restrict__ W, float* __restrict__ out)
{
    int w = (blockIdx.x * blockDim.x + threadIdx.x) >> 5;
    int lane = threadIdx.x & 31;
    if (w >= Nrows) return;
    const float* hr = H + (size_t)w * ADIM;
    float acc[8];
#pragma unroll
    for (int m = 0; m < 8; ++m) acc[m] = 0.f;
    for (int f = lane; f < ADIM; f += 32) {
        float hv = hr[f];
        const float* wr = W + f * 8;
#pragma unroll
        for (int m = 0; m < 8; ++m) acc[m] = fmaf(hv, wr[m], acc[m]);
    }
#pragma unroll
    for (int off = 16; off > 0; off >>= 1) {
#pragma unroll
        for (int m = 0; m < 8; ++m) acc[m] += __shfl_xor_sync(0xffffffffu, acc[m], off);
    }
    if (lane == 0) {
#pragma unroll
        for (int m = 0; m < 8; ++m) out[w * 8 + m] = acc[m];
    }
}

// ---------------- edge weight MLP (decomposed) + unified neighbor table write
__global__ void edgew_kernel(const int* __restrict__ nbr, int E, int Kk,
                             const float* __restrict__ dstPos, const float* __restrict__ srcPos,
                             const float* __restrict__ pSrc, const float* __restrict__ pDst,
                             const float* __restrict__ w1d, const float* __restrict__ b1,
                             const float* __restrict__ w2, const float* __restrict__ b2v,
                             int* __restrict__ Uidx, float* __restrict__ Uew,
                             int dstNodeBase, int slotOff, int srcGlobalOff)
{
    int e = blockIdx.x * blockDim.x + threadIdx.x;
    if (e >= E) return;
    int dl = e / Kk, slot = e - dl * Kk;
    int s = nbr[e];
    float dx = dstPos[dl * 3 + 0] - srcPos[s * 3 + 0];
    float dy = dstPos[dl * 3 + 1] - srcPos[s * 3 + 1];
    float dz = dstPos[dl * 3 + 2] - srcPos[s * 3 + 2];
    float ss = fmaf(dz, dz, fmaf(dy, dy, dx * dx));
    float d = sqrtf(ss + 1e-12f);
    float ew = b2v[0];
#pragma unroll
    for (int m = 0; m < 8; ++m) {
        float hmid = pSrc[s * 8 + m] + pDst[dl * 8 + m] + d * w1d[m] + b1[m];
        ew = fmaf(fmaxf(hmid, 0.f), w2[m], ew);
    }
    int un = dstNodeBase + dl;
    Uidx[un * MAXDEG + slotOff + slot] = srcGlobalOff + s;
    Uew[un * MAXDEG + slotOff + slot] = ew;
}

// ---------------- fused attention + residual + LayerNorm (+optional snapshot)
__global__ void attn_kernel(const float* __restrict__ qkv,
                            const int* __restrict__ Uidx, const float* __restrict__ Uew,
                            float* __restrict__ h,
                            const float* __restrict__ lng, const float* __restrict__ lnb,
                            float* __restrict__ snap,   // stride 640 if non-null
                            int nodeBase)
{
    const unsigned FULL = 0xffffffffu;
    __shared__ __align__(16) float vs[MAXDEG][132];
    __shared__ __align__(16) float qs[ADIM];
    __shared__ float logitS[MAXDEG][5];
    __shared__ int   srcs[MAXDEG];
    __shared__ float ews[MAXDEG];
    __shared__ float red[8];

    int n = nodeBase + blockIdx.x;
    int t = threadIdx.x;
    int warp = t >> 5, lane = t & 31;
    int deg = (n < NA) ? KAA : MAXDEG;

    if (t < deg) { srcs[t] = Uidx[n * MAXDEG + t]; ews[t] = Uew[n * MAXDEG + t]; }
    qs[t] = qkv[(size_t)n * QKVS + t];
    __syncthreads();

    float4 q4 = ((const float4*)qs)[lane];   // cols 4*lane..+3 (head = lane>>3)
    for (int j = warp; j < deg; j += 4) {
        const float4* base = (const float4*)(qkv + (size_t)srcs[j] * QKVS);
        float4 k4 = base[32 + lane];     // k row floats [128,256)
        float4 v4 = base[64 + lane];     // v row floats [256,384)
        *(float4*)&vs[j][lane << 2] = v4;
        float p = fmaf(k4.w, q4.w, fmaf(k4.z, q4.z, fmaf(k4.y, q4.y, k4.x * q4.x)));
        p += __shfl_xor_sync(FULL, p, 1);
        p += __shfl_xor_sync(FULL, p, 2);
        p += __shfl_xor_sync(FULL, p, 4);
        if ((lane & 7) == 0) logitS[j][lane >> 3] = p;
    }
    __syncthreads();

    int head = warp;
    float logit = -3.0e38f;
    if (lane < deg)
        logit = logitS[lane][head] * 0.17677669529663687f + ews[lane];
    float m = logit;
#pragma unroll
    for (int off = 16; off > 0; off >>= 1)
        m = fmaxf(m, __shfl_xor_sync(FULL, m, off));
    float z = (lane < deg) ? expf(logit - m) : 0.f;
    float ssum = z;
#pragma unroll
    for (int off = 16; off > 0; off >>= 1)
        ssum += __shfl_xor_sync(FULL, ssum, off);
    float alpha = z / (ssum + 1e-9f);

    float acc = 0.f;
    for (int j = 0; j < deg; ++j) {
        float a = __shfl_sync(FULL, alpha, j);
        acc = fmaf(a, vs[j][(head << 5) + lane], acc);
    }

    float y = h[(size_t)n * ADIM + t] + acc;
    float s1 = y, s2 = y * y;
#pragma unroll
    for (int off = 16; off > 0; off >>= 1) {
        s1 += __shfl_xor_sync(FULL, s1, off);
        s2 += __shfl_xor_sync(FULL, s2, off);
    }
    if (lane == 0) { red[warp] = s1; red[4 + warp] = s2; }
    __syncthreads();
    float t1 = red[0] + red[1] + red[2] + red[3];
    float t2 = red[4] + red[5] + red[6] + red[7];
    float mu = t1 * (1.0f / ADIM);
    float var = fmaxf(t2 * (1.0f / ADIM) - mu * mu, 0.f);
    float outv = (y - mu) * rsqrtf(var + 1e-5f) * lng[t] + lnb[t];
    h[(size_t)n * ADIM + t] = outv;
    if (snap != nullptr && n >= NA) snap[(size_t)(n - NA) * 640 + t] = outv;
}

// ---------------- host ----------------
extern "C" void kernel_launch(void* const* d_in, const int* in_sizes, int n_in,
                              void* d_out, int out_size)
{
    const float* atom_x    = (const float*)d_in[0];
    const float* atom_pos  = (const float*)d_in[1];
    const float* vox_x     = (const float*)d_in[2];
    const float* vox_pos   = (const float*)d_in[3];
    const float* w_atom_in = (const float*)d_in[4];
    const float* b_atom_in = (const float*)d_in[5];
    const float* w_vox_in  = (const float*)d_in[6];
    const float* b_vox_in  = (const float*)d_in[7];
    const float* aa_w1 = (const float*)d_in[8];
    const float* aa_b1 = (const float*)d_in[9];
    const float* aa_w2 = (const float*)d_in[10];
    const float* aa_b2 = (const float*)d_in[11];
    const float* av_w1 = (const float*)d_in[12];
    const float* av_b1 = (const float*)d_in[13];
    const float* av_w2 = (const float*)d_in[14];
    const float* av_b2 = (const float*)d_in[15];
    const float* vv_w1 = (const float*)d_in[16];
    const float* vv_b1 = (const float*)d_in[17];
    const float* vv_w2 = (const float*)d_in[18];
    const float* vv_b2 = (const float*)d_in[19];
    const float* wq   = (const float*)d_in[20];
    const float* wk   = (const float*)d_in[21];
    const float* wv   = (const float*)d_in[22];
    const float* ln_g = (const float*)d_in[23];
    const float* ln_b = (const float*)d_in[24];
    const float* w_o1 = (const float*)d_in[25];
    const float* b_o1 = (const float*)d_in[26];
    const float* w_o2 = (const float*)d_in[27];
    const float* b_o2 = (const float*)d_in[28];
    float* out = (float*)d_out;
    (void)in_sizes; (void)n_in; (void)out_size;

    float *h, *qkv, *wqkv, *Uew, *paas, *paad, *pavd, *pavs, *pvvs, *pvvd, *feat, *hidden;
    float4 *apos4, *vpos4;
    int *aaIdx, *avIdx, *vvIdx, *Uidx;
    cudaGetSymbolAddress((void**)&h, g_h);
    cudaGetSymbolAddress((void**)&qkv, g_qkv);
    cudaGetSymbolAddress((void**)&wqkv, g_wqkv);
    cudaGetSymbolAddress((void**)&apos4, g_apos4);
    cudaGetSymbolAddress((void**)&vpos4, g_vpos4);
    cudaGetSymbolAddress((void**)&aaIdx, g_aa);
    cudaGetSymbolAddress((void**)&avIdx, g_av);
    cudaGetSymbolAddress((void**)&vvIdx, g_vv);
    cudaGetSymbolAddress((void**)&Uidx, g_Uidx);
    cudaGetSymbolAddress((void**)&Uew, g_Uew);
    cudaGetSymbolAddress((void**)&paas, g_paas);
    cudaGetSymbolAddress((void**)&paad, g_paad);
    cudaGetSymbolAddress((void**)&pavd, g_pavd);
    cudaGetSymbolAddress((void**)&pavs, g_pavs);
    cudaGetSymbolAddress((void**)&pvvs, g_pvvs);
    cudaGetSymbolAddress((void**)&pvvd, g_pvvd);
    cudaGetSymbolAddress((void**)&feat, g_feat);
    cudaGetSymbolAddress((void**)&hidden, g_hidden);

    const float* voxh0 = h + (size_t)NA * ADIM;   // valid until layer loop mutates h

    static cudaStream_t sKnn = nullptr;
    static cudaEvent_t eFork = nullptr, eProj = nullptr, eEdges = nullptr;
    if (sKnn == nullptr) {
        cudaStreamCreate(&sKnn);
        cudaEventCreateWithFlags(&eFork, cudaEventDisableTiming);
        cudaEventCreateWithFlags(&eProj, cudaEventDisableTiming);
        cudaEventCreateWithFlags(&eEdges, cudaEventDisableTiming);
    }

    // fork: KNN chain on side stream, feature chain on main stream
    cudaEventRecord(eFork, 0);
    cudaStreamWaitEvent(sKnn, eFork, 0);

    // side stream: positions + KNN graphs (2 dst/warp, 16 dst/block)
    pack_pos<<<(NA + 255) / 256, 256, 0, sKnn>>>(atom_pos, apos4, NA);
    pack_pos<<<(NV + 255) / 256, 256, 0, sKnn>>>(vox_pos, vpos4, NV);
    knn_warp2<KAA, true><<<NA / 16, 256, 0, sKnn>>>(apos4, apos4, NA, aaIdx);
    knn_warp2<KVV, false><<<NV / 16, 256, 0, sKnn>>>(vpos4, apos4, NA, avIdx);
    knn_warp2<KVV, true><<<NV / 16, 256, 0, sKnn>>>(vpos4, vpos4, NV, vvIdx);

    // main stream: weight packing, input projections, edge-MLP projections
    pack_qkv<<<(LTOT * ADIM * ADIM + 255) / 256, 256>>>(wq, wk, wv, wqkv);
    gemm128<<<dim3(NA / 128, ADIM / 128), 256>>>(atom_x, w_atom_in, b_atom_in, h, FDIM, ADIM, 0, ADIM);
    gemm128<<<dim3(NV / 128, ADIM / 128), 256>>>(vox_x, w_vox_in, b_vox_in, (float*)voxh0, FDIM, ADIM, 0, ADIM);
    copy_to_feat<<<(NV * ADIM + 255) / 256, 256>>>(voxh0, feat);
    proj8_kernel<<<NA / 8, 256>>>(h, NA, aa_w1, paas);                 // aa: i0 = src atom
    proj8_kernel<<<NA / 8, 256>>>(h, NA, aa_w1 + 128 * 8, paad);       // aa: i1 = dst atom
    proj8_kernel<<<NV / 8, 256>>>(voxh0, NV, av_w1, pavd);             // av: i0 = vox (dst)
    proj8_kernel<<<NA / 8, 256>>>(h, NA, av_w1 + 128 * 8, pavs);       // av: i1 = atom (src)
    proj8_kernel<<<NV / 8, 256>>>(voxh0, NV, vv_w1, pvvs);             // vv: i0 = src vox
    proj8_kernel<<<NV / 8, 256>>>(voxh0, NV, vv_w1 + 128 * 8, pvvd);   // vv: i1 = dst vox
    cudaEventRecord(eProj, 0);

    // side stream: edge weights (needs KNN + projections)
    cudaStreamWaitEvent(sKnn, eProj, 0);
    edgew_kernel<<<(NA * KAA + 255) / 256, 256, 0, sKnn>>>(aaIdx, NA * KAA, KAA, atom_pos, atom_pos,
        paas, paad, aa_w1 + 256 * 8, aa_b1, aa_w2, aa_b2, Uidx, Uew, 0, 0, 0);
    edgew_kernel<<<(NV * KVV + 255) / 256, 256, 0, sKnn>>>(avIdx, NV * KVV, KVV, vox_pos, atom_pos,
        pavs, pavd, av_w1 + 256 * 8, av_b1, av_w2, av_b2, Uidx, Uew, NA, 0, 0);
    edgew_kernel<<<(NV * KVV + 255) / 256, 256, 0, sKnn>>>(vvIdx, NV * KVV, KVV, vox_pos, vox_pos,
        pvvs, pvvd, vv_w1 + 256 * 8, vv_b1, vv_w2, vv_b2, Uidx, Uew, NA, KVV, NA);
    cudaEventRecord(eEdges, sKnn);

    // main stream: first QKV GEMM (tf32 tensor cores) overlaps edge weights
    gemm128_tf32<<<dim3(NN / 128, QKVS / 128), 256>>>(h, wqkv, qkv, ADIM, QKVS, QKVS);
    cudaStreamWaitEvent(0, eEdges, 0);   // join before first attention

    // attention stack (8 layers); last layer only needs vox nodes
    for (int li = 0; li < LTOT; ++li) {
        if (li > 0)
            gemm128_tf32<<<dim3(NN / 128, QKVS / 128), 256>>>(h, wqkv + (size_t)li * ADIM * QKVS,
                                                              qkv, ADIM, QKVS, QKVS);
        float* snap = (li & 1) ? (feat + (size_t)((li >> 1) + 1) * ADIM) : nullptr;
        if (li == LTOT - 1) {
            attn_kernel<<<NV, 128>>>(qkv, Uidx, Uew, h,
                                     ln_g + (size_t)li * ADIM, ln_b + (size_t)li * ADIM, snap, NA);
        } else {
            attn_kernel<<<NN, 128>>>(qkv, Uidx, Uew, h,
                                     ln_g + (size_t)li * ADIM, ln_b + (size_t)li * ADIM, snap, 0);
        }
    }

    // output head: feat [NV,640] -> relu -> [NV,128] -> [NV,128]
    gemm128<<<dim3(NV / 128, ADIM / 128), 256>>>(feat, w_o1, b_o1, hidden, 640, ADIM, 1, ADIM);
    gemm128<<<dim3(NV / 128, OUTD / 128), 256>>>(hidden, w_o2, b_o2, out, ADIM, OUTD, 0, OUTD);
}

// round 16
// speedup vs baseline: 1.3332x; 1.3332x over previous
#include <cuda_runtime.h>
#include <math.h>

#define NA 8192
#define NV 4096
#define NN 12288      // NA + NV
#define FDIM 64
#define ADIM 128
#define QKVS 384
#define KAA 10
#define KVV 15
#define MAXDEG 30
#define LTOT 8
#define OUTD 128

// ---------------- device scratch (no allocations allowed) ----------------
__device__ float  g_h[NN * ADIM];
__device__ float  g_qkv[NN * QKVS];
__device__ float  g_wqkv[LTOT * ADIM * QKVS];
__device__ float4 g_apos4[NA];
__device__ float4 g_vpos4[NV];
__device__ int    g_aa[NA * KAA];
__device__ int    g_av[NV * KVV];
__device__ int    g_vv[NV * KVV];
__device__ int    g_Uidx[NN * MAXDEG];
__device__ float  g_Uew[NN * MAXDEG];
__device__ float  g_paas[NA * 8];
__device__ float  g_paad[NA * 8];
__device__ float  g_pavd[NV * 8];
__device__ float  g_pavs[NA * 8];
__device__ float  g_pvvs[NV * 8];
__device__ float  g_pvvd[NV * 8];
__device__ float  g_feat[NV * 640];
__device__ float  g_hidden[NV * ADIM];

// packed f32x2 FMA: d = a * b + d (per 32-bit lane, IEEE fp32 — bit-identical
// to scalar FFMA). Blackwell-only; ptxas never emits FFMA2 from C++.
#define FMA_F32X2(d, a, b) \
    asm("fma.rn.f32x2 %0, %1, %2, %0;" : "+l"(d) : "l"(a), "l"(b))

// ---------------- double-buffered fp32 big-tile GEMM with FFMA2 ----------------
// C[M,N] = A[M,K] @ B[K,N] (+bias)(+relu); grid=(M/128,N/128), 256 thr, 8x8/thr
__global__ __launch_bounds__(256, 2)
void gemm128(const float* __restrict__ A, const float* __restrict__ B,
             const float* __restrict__ bias, float* __restrict__ C,
             int K, int N, int doRelu, int ldc)
{
    __shared__ __align__(16) float As[2][8][128];
    __shared__ __align__(16) float Bs[2][8][128];
    int tid = threadIdx.x;
    int bm = blockIdx.x << 7, bn = blockIdx.y << 7;
    int arow = tid >> 1, acol = (tid & 1) << 2;
    int brow = tid >> 5, bcol = (tid & 31) << 2;
    int tx = tid & 15, ty = tid >> 4;

    const float* Ap = A + (size_t)(bm + arow) * K + acol;
    const float* Bp = B + (size_t)brow * N + bn + bcol;

    // 8x8 fp32 accumulators as 8x4 packed f32x2 (zero bits == {+0.f, +0.f})
    unsigned long long acc2[8][4];
#pragma unroll
    for (int i = 0; i < 8; ++i)
#pragma unroll
        for (int j = 0; j < 4; ++j) acc2[i][j] = 0ull;

    {
        float4 av = *(const float4*)(Ap);
        float4 bv = *(const float4*)(Bp);
        As[0][acol + 0][arow] = av.x;
        As[0][acol + 1][arow] = av.y;
        As[0][acol + 2][arow] = av.z;
        As[0][acol + 3][arow] = av.w;
        *(float4*)&Bs[0][brow][bcol] = bv;
    }
    __syncthreads();

    int buf = 0;
    for (int k0 = 0; k0 < K; k0 += 8) {
        bool more = (k0 + 8) < K;
        float4 av2, bv2;
        if (more) {
            av2 = *(const float4*)(Ap + k0 + 8);
            bv2 = *(const float4*)(Bp + (size_t)(k0 + 8) * N);
        }
#pragma unroll
        for (int kk = 0; kk < 8; ++kk) {
            // B pairs load directly as 64-bit lanes (no repack needed)
            ulonglong2 b01 = *(const ulonglong2*)&Bs[buf][kk][tx << 3];
            ulonglong2 b23 = *(const ulonglong2*)&Bs[buf][kk][(tx << 3) + 4];
            unsigned long long br2[4] = { b01.x, b01.y, b23.x, b23.y };
            float4 a03 = *(const float4*)&As[buf][kk][ty << 3];
            float4 a47 = *(const float4*)&As[buf][kk][(ty << 3) + 4];
            float ar[8] = { a03.x, a03.y, a03.z, a03.w, a47.x, a47.y, a47.z, a47.w };
#pragma unroll
            for (int i = 0; i < 8; ++i) {
                unsigned ai = __float_as_uint(ar[i]);
                unsigned long long a2;
                asm("mov.b64 %0, {%1, %1};" : "=l"(a2) : "r"(ai));
#pragma unroll
                for (int j = 0; j < 4; ++j)
                    FMA_F32X2(acc2[i][j], a2, br2[j]);
            }
        }
        if (more) {
            As[buf ^ 1][acol + 0][arow] = av2.x;
            As[buf ^ 1][acol + 1][arow] = av2.y;
            As[buf ^ 1][acol + 2][arow] = av2.z;
            As[buf ^ 1][acol + 3][arow] = av2.w;
            *(float4*)&Bs[buf ^ 1][brow][bcol] = bv2;
            __syncthreads();
            buf ^= 1;
        }
    }

#pragma unroll
    for (int i = 0; i < 8; ++i) {
        int r = bm + (ty << 3) + i;
        float* Cr = C + (size_t)r * ldc + bn + (tx << 3);
#pragma unroll
        for (int j = 0; j < 4; ++j) {
            unsigned lo, hi;
            asm("mov.b64 {%0, %1}, %2;" : "=r"(lo), "=r"(hi) : "l"(acc2[i][j]));
            float v0 = __uint_as_float(lo), v1 = __uint_as_float(hi);
            int c = bn + (tx << 3) + 2 * j;
            if (bias) { v0 += bias[c]; v1 += bias[c + 1]; }
            if (doRelu) { v0 = fmaxf(v0, 0.f); v1 = fmaxf(v1, 0.f); }
            Cr[2 * j] = v0;
            Cr[2 * j + 1] = v1;
        }
    }
}

// ---------------- position packing: (x, y, z, |p|^2) ----------------
__global__ void pack_pos(const float* __restrict__ pos, float4* __restrict__ out, int n)
{
    int i = blockIdx.x * blockDim.x + threadIdx.x;
    if (i >= n) return;
    float x = pos[i * 3 + 0], y = pos[i * 3 + 1], z = pos[i * 3 + 2];
    out[i] = make_float4(x, y, z, x * x + y * y + z * z);
}

// ---------------- pack wq|wk|wv -> [L,128,384] ----------------
__global__ void pack_qkv(const float* __restrict__ wq, const float* __restrict__ wk,
                         const float* __restrict__ wv, float* __restrict__ out)
{
    int i = blockIdx.x * blockDim.x + threadIdx.x;
    if (i >= LTOT * ADIM * ADIM) return;
    int li = i / (ADIM * ADIM);
    int r = (i / ADIM) % ADIM;
    int c = i % ADIM;
    float* o = out + ((size_t)li * ADIM + r) * QKVS;
    o[c] = wq[i];
    o[ADIM + c] = wk[i];
    o[2 * ADIM + c] = wv[i];
}

// ---------------- strided copy of vox h0 into feat cols [0:128) ----------------
__global__ void copy_to_feat(const float* __restrict__ src, float* __restrict__ feat)
{
    int i = blockIdx.x * blockDim.x + threadIdx.x;
    if (i >= NV * ADIM) return;
    int r = i >> 7, c = i & 127;
    feat[(size_t)r * 640 + c] = src[i];
}

// ---------------- warp-cooperative brute-force KNN (1 dst per warp) ----------------
// Distributed sorted top-K across lanes (lane j = j-th smallest (d2,idx), exact
// lexicographic == jax top_k stable tie-break); ballot + whole-warp shuffle-up
// insert. d2 = |a|^2 + |b|^2 - 2 a.b exactly as reference.
template <int KK, bool EXCL>
__global__ __launch_bounds__(256)
void knn_warp(const float4* __restrict__ dpos4, const float4* __restrict__ spos4,
              int Ns, int* __restrict__ outIdx)
{
    const int TS = 1024;
    const unsigned FULL = 0xffffffffu;
    __shared__ float4 s4[TS];
    int lane = threadIdx.x & 31;
    int warp = threadIdx.x >> 5;
    int dst = blockIdx.x * 8 + warp;

    float4 p = dpos4[dst];

    float ld = __int_as_float(0x7f800000);  // +inf
    int   li = 0x7fffffff;
    float T  = ld;
    int   Ti = li;

    for (int t0 = 0; t0 < Ns; t0 += TS) {
        int tn = Ns - t0; if (tn > TS) tn = TS;
        __syncthreads();
        for (int i = threadIdx.x; i < tn; i += 256) s4[i] = spos4[t0 + i];
        __syncthreads();
        for (int j = lane; j < tn; j += 32) {
            int si = t0 + j;
            float4 qv = s4[j];
            float dot = fmaf(p.z, qv.z, fmaf(p.y, qv.y, p.x * qv.x));
            float d2 = (p.w + qv.w) - 2.0f * dot;
            if (EXCL && si == dst) { d2 = __int_as_float(0x7f800000); si = 0x7fffffff; }
            bool pass = (d2 < T) || (d2 == T && si < Ti);
            unsigned m = __ballot_sync(FULL, pass);
            while (m) {
                int s = __ffs(m) - 1;
                float cd = __shfl_sync(FULL, d2, s);
                int   ci = __shfl_sync(FULL, si, s);
                bool before = (cd < ld) || (cd == ld && ci < li);
                unsigned bm = __ballot_sync(FULL, before);
                float ud = __shfl_up_sync(FULL, ld, 1);
                int   ui = __shfl_up_sync(FULL, li, 1);
                int firstBefore = __ffs(bm) - 1;
                if (before) {
                    if (lane == firstBefore) { ld = cd; li = ci; }
                    else                     { ld = ud; li = ui; }
                }
                T  = __shfl_sync(FULL, ld, KK - 1);
                Ti = __shfl_sync(FULL, li, KK - 1);
                pass = pass && (lane > s) && ((d2 < T) || (d2 == T && si < Ti));
                m = __ballot_sync(FULL, pass);
            }
        }
    }
    if (lane < KK) outIdx[dst * KK + lane] = li;
}

// ---------------- per-row 128->8 projection (edge MLP first layer halves)
__global__ void proj8_kernel(const float* __restrict__ H, int Nrows,
                             const float* __restrict__ W, float* __restrict__ out)
{
    int w = (blockIdx.x * blockDim.x + threadIdx.x) >> 5;
    int lane = threadIdx.x & 31;
    if (w >= Nrows) return;
    const float* hr = H + (size_t)w * ADIM;
    float acc[8];
#pragma unroll
    for (int m = 0; m < 8; ++m) acc[m] = 0.f;
    for (int f = lane; f < ADIM; f += 32) {
        float hv = hr[f];
        const float* wr = W + f * 8;
#pragma unroll
        for (int m = 0; m < 8; ++m) acc[m] = fmaf(hv, wr[m], acc[m]);
    }
#pragma unroll
    for (int off = 16; off > 0; off >>= 1) {
#pragma unroll
        for (int m = 0; m < 8; ++m) acc[m] += __shfl_xor_sync(0xffffffffu, acc[m], off);
    }
    if (lane == 0) {
#pragma unroll
        for (int m = 0; m < 8; ++m) out[w * 8 + m] = acc[m];
    }
}

// ---------------- edge weight MLP (decomposed) + unified neighbor table write
__global__ void edgew_kernel(const int* __restrict__ nbr, int E, int Kk,
                             const float* __restrict__ dstPos, const float* __restrict__ srcPos,
                             const float* __restrict__ pSrc, const float* __restrict__ pDst,
                             const float* __restrict__ w1d, const float* __restrict__ b1,
                             const float* __restrict__ w2, const float* __restrict__ b2v,
                             int* __restrict__ Uidx, float* __restrict__ Uew,
                             int dstNodeBase, int slotOff, int srcGlobalOff)
{
    int e = blockIdx.x * blockDim.x + threadIdx.x;
    if (e >= E) return;
    int dl = e / Kk, slot = e - dl * Kk;
    int s = nbr[e];
    float dx = dstPos[dl * 3 + 0] - srcPos[s * 3 + 0];
    float dy = dstPos[dl * 3 + 1] - srcPos[s * 3 + 1];
    float dz = dstPos[dl * 3 + 2] - srcPos[s * 3 + 2];
    float ss = fmaf(dz, dz, fmaf(dy, dy, dx * dx));
    float d = sqrtf(ss + 1e-12f);
    float ew = b2v[0];
#pragma unroll
    for (int m = 0; m < 8; ++m) {
        float hmid = pSrc[s * 8 + m] + pDst[dl * 8 + m] + d * w1d[m] + b1[m];
        ew = fmaf(fmaxf(hmid, 0.f), w2[m], ew);
    }
    int un = dstNodeBase + dl;
    Uidx[un * MAXDEG + slotOff + slot] = srcGlobalOff + s;
    Uew[un * MAXDEG + slotOff + slot] = ew;
}

// ---------------- fused attention + residual + LayerNorm (+optional snapshot)
// one block (128 threads) per dst node; q|k|v packed row stride 384.
// k rows never hit smem: each float4 k-load folds into a partial q.k dot,
// reduced over 8-lane groups into logitS[deg][head]. v staged via float4.
__global__ void attn_kernel(const float* __restrict__ qkv,
                            const int* __restrict__ Uidx, const float* __restrict__ Uew,
                            float* __restrict__ h,
                            const float* __restrict__ lng, const float* __restrict__ lnb,
                            float* __restrict__ snap,   // stride 640 if non-null
                            int nodeBase)
{
    const unsigned FULL = 0xffffffffu;
    __shared__ __align__(16) float vs[MAXDEG][132];
    __shared__ __align__(16) float qs[ADIM];
    __shared__ float logitS[MAXDEG][5];
    __shared__ int   srcs[MAXDEG];
    __shared__ float ews[MAXDEG];
    __shared__ float red[8];

    int n = nodeBase + blockIdx.x;
    int t = threadIdx.x;
    int warp = t >> 5, lane = t & 31;
    int deg = (n < NA) ? KAA : MAXDEG;

    if (t < deg) { srcs[t] = Uidx[n * MAXDEG + t]; ews[t] = Uew[n * MAXDEG + t]; }
    qs[t] = qkv[(size_t)n * QKVS + t];
    __syncthreads();

    float4 q4 = ((const float4*)qs)[lane];   // cols 4*lane..+3 (head = lane>>3)
    for (int j = warp; j < deg; j += 4) {
        const float4* base = (const float4*)(qkv + (size_t)srcs[j] * QKVS);
        float4 k4 = base[32 + lane];     // k row floats [128,256)
        float4 v4 = base[64 + lane];     // v row floats [256,384)
        *(float4*)&vs[j][lane << 2] = v4;
        float p = fmaf(k4.w, q4.w, fmaf(k4.z, q4.z, fmaf(k4.y, q4.y, k4.x * q4.x)));
        p += __shfl_xor_sync(FULL, p, 1);
        p += __shfl_xor_sync(FULL, p, 2);
        p += __shfl_xor_sync(FULL, p, 4);
        if ((lane & 7) == 0) logitS[j][lane >> 3] = p;
    }
    __syncthreads();

    int head = warp;
    float logit = -3.0e38f;
    if (lane < deg)
        logit = logitS[lane][head] * 0.17677669529663687f + ews[lane];
    float m = logit;
#pragma unroll
    for (int off = 16; off > 0; off >>= 1)
        m = fmaxf(m, __shfl_xor_sync(FULL, m, off));
    float z = (lane < deg) ? expf(logit - m) : 0.f;
    float ssum = z;
#pragma unroll
    for (int off = 16; off > 0; off >>= 1)
        ssum += __shfl_xor_sync(FULL, ssum, off);
    float alpha = z / (ssum + 1e-9f);

    float acc = 0.f;
    for (int j = 0; j < deg; ++j) {
        float a = __shfl_sync(FULL, alpha, j);
        acc = fmaf(a, vs[j][(head << 5) + lane], acc);
    }

    float y = h[(size_t)n * ADIM + t] + acc;
    float s1 = y, s2 = y * y;
#pragma unroll
    for (int off = 16; off > 0; off >>= 1) {
        s1 += __shfl_xor_sync(FULL, s1, off);
        s2 += __shfl_xor_sync(FULL, s2, off);
    }
    if (lane == 0) { red[warp] = s1; red[4 + warp] = s2; }
    __syncthreads();
    float t1 = red[0] + red[1] + red[2] + red[3];
    float t2 = red[4] + red[5] + red[6] + red[7];
    float mu = t1 * (1.0f / ADIM);
    float var = fmaxf(t2 * (1.0f / ADIM) - mu * mu, 0.f);
    float outv = (y - mu) * rsqrtf(var + 1e-5f) * lng[t] + lnb[t];
    h[(size_t)n * ADIM + t] = outv;
    if (snap != nullptr && n >= NA) snap[(size_t)(n - NA) * 640 + t] = outv;
}

// ---------------- host ----------------
extern "C" void kernel_launch(void* const* d_in, const int* in_sizes, int n_in,
                              void* d_out, int out_size)
{
    const float* atom_x    = (const float*)d_in[0];
    const float* atom_pos  = (const float*)d_in[1];
    const float* vox_x     = (const float*)d_in[2];
    const float* vox_pos   = (const float*)d_in[3];
    const float* w_atom_in = (const float*)d_in[4];
    const float* b_atom_in = (const float*)d_in[5];
    const float* w_vox_in  = (const float*)d_in[6];
    const float* b_vox_in  = (const float*)d_in[7];
    const float* aa_w1 = (const float*)d_in[8];
    const float* aa_b1 = (const float*)d_in[9];
    const float* aa_w2 = (const float*)d_in[10];
    const float* aa_b2 = (const float*)d_in[11];
    const float* av_w1 = (const float*)d_in[12];
    const float* av_b1 = (const float*)d_in[13];
    const float* av_w2 = (const float*)d_in[14];
    const float* av_b2 = (const float*)d_in[15];
    const float* vv_w1 = (const float*)d_in[16];
    const float* vv_b1 = (const float*)d_in[17];
    const float* vv_w2 = (const float*)d_in[18];
    const float* vv_b2 = (const float*)d_in[19];
    const float* wq   = (const float*)d_in[20];
    const float* wk   = (const float*)d_in[21];
    const float* wv   = (const float*)d_in[22];
    const float* ln_g = (const float*)d_in[23];
    const float* ln_b = (const float*)d_in[24];
    const float* w_o1 = (const float*)d_in[25];
    const float* b_o1 = (const float*)d_in[26];
    const float* w_o2 = (const float*)d_in[27];
    const float* b_o2 = (const float*)d_in[28];
    float* out = (float*)d_out;
    (void)in_sizes; (void)n_in; (void)out_size;

    float *h, *qkv, *wqkv, *Uew, *paas, *paad, *pavd, *pavs, *pvvs, *pvvd, *feat, *hidden;
    float4 *apos4, *vpos4;
    int *aaIdx, *avIdx, *vvIdx, *Uidx;
    cudaGetSymbolAddress((void**)&h, g_h);
    cudaGetSymbolAddress((void**)&qkv, g_qkv);
    cudaGetSymbolAddress((void**)&wqkv, g_wqkv);
    cudaGetSymbolAddress((void**)&apos4, g_apos4);
    cudaGetSymbolAddress((void**)&vpos4, g_vpos4);
    cudaGetSymbolAddress((void**)&aaIdx, g_aa);
    cudaGetSymbolAddress((void**)&avIdx, g_av);
    cudaGetSymbolAddress((void**)&vvIdx, g_vv);
    cudaGetSymbolAddress((void**)&Uidx, g_Uidx);
    cudaGetSymbolAddress((void**)&Uew, g_Uew);
    cudaGetSymbolAddress((void**)&paas, g_paas);
    cudaGetSymbolAddress((void**)&paad, g_paad);
    cudaGetSymbolAddress((void**)&pavd, g_pavd);
    cudaGetSymbolAddress((void**)&pavs, g_pavs);
    cudaGetSymbolAddress((void**)&pvvs, g_pvvs);
    cudaGetSymbolAddress((void**)&pvvd, g_pvvd);
    cudaGetSymbolAddress((void**)&feat, g_feat);
    cudaGetSymbolAddress((void**)&hidden, g_hidden);

    const float* voxh0 = h + (size_t)NA * ADIM;   // valid until layer loop mutates h

    static cudaStream_t sKnn = nullptr;
    static cudaEvent_t eFork = nullptr, eProj = nullptr, eEdges = nullptr;
    if (sKnn == nullptr) {
        cudaStreamCreate(&sKnn);
        cudaEventCreateWithFlags(&eFork, cudaEventDisableTiming);
        cudaEventCreateWithFlags(&eProj, cudaEventDisableTiming);
        cudaEventCreateWithFlags(&eEdges, cudaEventDisableTiming);
    }

    // fork: KNN chain on side stream, feature chain on main stream
    cudaEventRecord(eFork, 0);
    cudaStreamWaitEvent(sKnn, eFork, 0);

    // side stream: positions + KNN graphs (1 dst/warp, 8 dst/block)
    pack_pos<<<(NA + 255) / 256, 256, 0, sKnn>>>(atom_pos, apos4, NA);
    pack_pos<<<(NV + 255) / 256, 256, 0, sKnn>>>(vox_pos, vpos4, NV);
    knn_warp<KAA, true><<<NA / 8, 256, 0, sKnn>>>(apos4, apos4, NA, aaIdx);
    knn_warp<KVV, false><<<NV / 8, 256, 0, sKnn>>>(vpos4, apos4, NA, avIdx);
    knn_warp<KVV, true><<<NV / 8, 256, 0, sKnn>>>(vpos4, vpos4, NV, vvIdx);

    // main stream: weight packing, input projections, edge-MLP projections
    pack_qkv<<<(LTOT * ADIM * ADIM + 255) / 256, 256>>>(wq, wk, wv, wqkv);
    gemm128<<<dim3(NA / 128, ADIM / 128), 256>>>(atom_x, w_atom_in, b_atom_in, h, FDIM, ADIM, 0, ADIM);
    gemm128<<<dim3(NV / 128, ADIM / 128), 256>>>(vox_x, w_vox_in, b_vox_in, (float*)voxh0, FDIM, ADIM, 0, ADIM);
    copy_to_feat<<<(NV * ADIM + 255) / 256, 256>>>(voxh0, feat);
    proj8_kernel<<<NA / 8, 256>>>(h, NA, aa_w1, paas);                 // aa: i0 = src atom
    proj8_kernel<<<NA / 8, 256>>>(h, NA, aa_w1 + 128 * 8, paad);       // aa: i1 = dst atom
    proj8_kernel<<<NV / 8, 256>>>(voxh0, NV, av_w1, pavd);             // av: i0 = vox (dst)
    proj8_kernel<<<NA / 8, 256>>>(h, NA, av_w1 + 128 * 8, pavs);       // av: i1 = atom (src)
    proj8_kernel<<<NV / 8, 256>>>(voxh0, NV, vv_w1, pvvs);             // vv: i0 = src vox
    proj8_kernel<<<NV / 8, 256>>>(voxh0, NV, vv_w1 + 128 * 8, pvvd);   // vv: i1 = dst vox
    cudaEventRecord(eProj, 0);

    // side stream: edge weights (needs KNN + projections)
    cudaStreamWaitEvent(sKnn, eProj, 0);
    edgew_kernel<<<(NA * KAA + 255) / 256, 256, 0, sKnn>>>(aaIdx, NA * KAA, KAA, atom_pos, atom_pos,
        paas, paad, aa_w1 + 256 * 8, aa_b1, aa_w2, aa_b2, Uidx, Uew, 0, 0, 0);
    edgew_kernel<<<(NV * KVV + 255) / 256, 256, 0, sKnn>>>(avIdx, NV * KVV, KVV, vox_pos, atom_pos,
        pavs, pavd, av_w1 + 256 * 8, av_b1, av_w2, av_b2, Uidx, Uew, NA, 0, 0);
    edgew_kernel<<<(NV * KVV + 255) / 256, 256, 0, sKnn>>>(vvIdx, NV * KVV, KVV, vox_pos, vox_pos,
        pvvs, pvvd, vv_w1 + 256 * 8, vv_b1, vv_w2, vv_b2, Uidx, Uew, NA, KVV, NA);
    cudaEventRecord(eEdges, sKnn);

    // main stream: first QKV GEMM overlaps edge-weight computation
    gemm128<<<dim3(NN / 128, QKVS / 128), 256>>>(h, wqkv, nullptr, qkv, ADIM, QKVS, 0, QKVS);
    cudaStreamWaitEvent(0, eEdges, 0);   // join before first attention

    // attention stack (8 layers); last layer only needs vox nodes
    for (int li = 0; li < LTOT; ++li) {
        if (li > 0)
            gemm128<<<dim3(NN / 128, QKVS / 128), 256>>>(h, wqkv + (size_t)li * ADIM * QKVS,
                                                         nullptr, qkv, ADIM, QKVS, 0, QKVS);
        float* snap = (li & 1) ? (feat + (size_t)((li >> 1) + 1) * ADIM) : nullptr;
        if (li == LTOT - 1) {
            attn_kernel<<<NV, 128>>>(qkv, Uidx, Uew, h,
                                     ln_g + (size_t)li * ADIM, ln_b + (size_t)li * ADIM, snap, NA);
        } else {
            attn_kernel<<<NN, 128>>>(qkv, Uidx, Uew, h,
                                     ln_g + (size_t)li * ADIM, ln_b + (size_t)li * ADIM, snap, 0);
        }
    }

    // output head: feat [NV,640] -> relu -> [NV,128] -> [NV,128]
    gemm128<<<dim3(NV / 128, ADIM / 128), 256>>>(feat, w_o1, b_o1, hidden, 640, ADIM, 1, ADIM);
    gemm128<<<dim3(NV / 128, OUTD / 128), 256>>>(hidden, w_o2, b_o2, out, ADIM, OUTD, 0, OUTD);
}